// round 3
// baseline (speedup 1.0000x reference)
#include <cuda_runtime.h>

// ---------------------------------------------------------------------------
// Edge2NodeFeatures: h = LN(relu(A @ W + b)); out[n] = (scatter_add dst + src) / deg
// A: [E,64] f32, W: [64,128] f32, edge_index: [2,E] i64 (or i32 — detected),
// out: [N,128] f32.
// ---------------------------------------------------------------------------

#define NB 4                     // edges per batch in main kernel
#define DEG_CAP (1 << 20)

__device__ float g_degree[DEG_CAP];

// ---- packed f32x2 helpers (FFMA2 path; only reachable via PTX) ----
__device__ __forceinline__ unsigned long long pack2(float lo, float hi) {
    unsigned long long r;
    asm("mov.b64 %0, {%1, %2};" : "=l"(r) : "f"(lo), "f"(hi));
    return r;
}
__device__ __forceinline__ unsigned long long fma2(unsigned long long a,
                                                   unsigned long long w,
                                                   unsigned long long c) {
    unsigned long long d;
    asm("fma.rn.f32x2 %0, %1, %2, %3;" : "=l"(d) : "l"(a), "l"(w), "l"(c));
    return d;
}
__device__ __forceinline__ float2 unpack2(unsigned long long v) {
    unsigned int lo, hi;
    asm("mov.b64 {%0, %1}, %2;" : "=r"(lo), "=r"(hi) : "l"(v));
    return make_float2(__uint_as_float(lo), __uint_as_float(hi));
}

// Detect whether edge_index is int64 or int32 (JAX x64-off downcast).
// int32 data read as i64 packs two indices; high half nonzero => value >= 2^32.
__device__ __forceinline__ bool idx_is_64(const long long* eidx, int N) {
    bool ok = true;
#pragma unroll
    for (int t = 0; t < 4; t++) {
        unsigned long long v = (unsigned long long)eidx[t];
        if (v >= (unsigned long long)N) ok = false;
    }
    return ok;
}

__global__ void zero_kernel(float4* out4, int n4, int N) {
    int i = blockIdx.x * blockDim.x + threadIdx.x;
    if (i < n4) out4[i] = make_float4(0.f, 0.f, 0.f, 0.f);
    if (i < N)  g_degree[i] = 0.f;
}

// ---------------------------------------------------------------------------
// Main fused kernel: thread j owns output column j (W column in 64 registers,
// stored as 32 duplicate-free k-pairs for fma.rn.f32x2). 4 edges per batch.
// ---------------------------------------------------------------------------
__global__ void __launch_bounds__(128)
edge2node_main(const float* __restrict__ edge_attr,
               const float* __restrict__ W,
               const float* __restrict__ bias,
               const float* __restrict__ gamma,
               const float* __restrict__ beta,
               const long long* __restrict__ eidx,
               float* __restrict__ out,
               int E, int nbatch, int N)
{
    __shared__ __align__(16) float s_a[NB * 64];     // staged edge_attr rows
    __shared__ __align__(16) float s_h[NB * 128];    // normalized h for scatter
    __shared__ float2 s_part[4][NB];                 // per-warp (sum, sumsq)
    __shared__ long long s_idx[2 * NB];              // [src x NB, dst x NB]

    const int j = threadIdx.x;          // column 0..127
    const int lane = j & 31, warp = j >> 5;
    const bool is64 = idx_is_64(eidx, N);

    // W column j as 32 packed (k, k+1) pairs -> 64 registers
    unsigned long long wp[32];
#pragma unroll
    for (int kk = 0; kk < 32; kk++)
        wp[kk] = pack2(W[(2 * kk) * 128 + j], W[(2 * kk + 1) * 128 + j]);
    const float bj = bias[j], gj = gamma[j], btj = beta[j];

    for (int batch = blockIdx.x; batch < nbatch; batch += (int)gridDim.x) {
        const int e0 = batch * NB;
        // stage NB rows of edge_attr (NB*64 floats = NB*16 float4, contiguous)
        if (j < NB * 16)
            ((float4*)s_a)[j] = ((const float4*)(edge_attr + (size_t)e0 * 64))[j];
        if (j < NB) {
            s_idx[j] = is64 ? eidx[e0 + j]
                            : (long long)((const int*)eidx)[e0 + j];
            s_idx[NB + j] = is64 ? eidx[(size_t)E + e0 + j]
                                 : (long long)((const int*)eidx)[(size_t)E + e0 + j];
        }
        __syncthreads();

        unsigned long long accA[NB], accB[NB];
#pragma unroll
        for (int m = 0; m < NB; m++) { accA[m] = 0ull; accB[m] = 0ull; }

        // mainloop: 16 x (4 k-values) per edge, packed FMAs
#pragma unroll
        for (int kk4 = 0; kk4 < 16; kk4++) {
#pragma unroll
            for (int m = 0; m < NB; m++) {
                const ulonglong2 av =
                    *(const ulonglong2*)(s_a + m * 64 + kk4 * 4);  // LDS.128 broadcast
                accA[m] = fma2(av.x, wp[2 * kk4],     accA[m]);
                accB[m] = fma2(av.y, wp[2 * kk4 + 1], accB[m]);
            }
        }

        float h[NB];
#pragma unroll
        for (int m = 0; m < NB; m++) {
            float2 a = unpack2(accA[m]);
            float2 b2 = unpack2(accB[m]);
            h[m] = fmaxf((a.x + a.y) + (b2.x + b2.y) + bj, 0.0f);
        }

        // warp-level partial (sum, sumsq) per edge
#pragma unroll
        for (int m = 0; m < NB; m++) {
            float s = h[m], s2 = h[m] * h[m];
#pragma unroll
            for (int off = 16; off > 0; off >>= 1) {
                s  += __shfl_xor_sync(0xffffffffu, s,  off);
                s2 += __shfl_xor_sync(0xffffffffu, s2, off);
            }
            if (lane == 0) s_part[warp][m] = make_float2(s, s2);
        }
        __syncthreads();

        // combine 4 warp partials, normalize, stage for scatter
#pragma unroll
        for (int m = 0; m < NB; m++) {
            float2 p0 = s_part[0][m], p1 = s_part[1][m];
            float2 p2 = s_part[2][m], p3 = s_part[3][m];
            float sum = (p0.x + p1.x) + (p2.x + p3.x);
            float ss  = (p0.y + p1.y) + (p2.y + p3.y);
            float mu  = sum * (1.0f / 128.0f);
            float var = ss * (1.0f / 128.0f) - mu * mu;
            float rs  = rsqrtf(var + 1e-5f);
            s_h[m * 128 + j] = (h[m] - mu) * rs * gj + btj;
        }
        __syncthreads();

        // scatter: NB edges x {src,dst} x 32 quads = 256 v4 reds, 2 per thread
#pragma unroll
        for (int r = 0; r < 2; r++) {
            int item = j + 128 * r;           // 0..255
            int m    = item >> 6;             // edge within batch
            int sgrp = (item >> 5) & 1;       // 0=src row, 1=dst row
            int q    = item & 31;             // float4 quad within 128 cols
            long long node = s_idx[sgrp * NB + m];
            float4 v = ((const float4*)(s_h + m * 128))[q];
            float* p = out + node * 128 + q * 4;
            asm volatile("red.global.add.v4.f32 [%0], {%1,%2,%3,%4};"
                         :: "l"(p), "f"(v.x), "f"(v.y), "f"(v.z), "f"(v.w)
                         : "memory");
        }
        if (j < 2 * NB) atomicAdd(&g_degree[(int)s_idx[j]], 1.0f);
        __syncthreads();
    }
}

// Slow path for E % NB tail edges (one block per edge).
__global__ void __launch_bounds__(128)
edge2node_tail(const float* __restrict__ edge_attr,
               const float* __restrict__ W,
               const float* __restrict__ bias,
               const float* __restrict__ gamma,
               const float* __restrict__ beta,
               const long long* __restrict__ eidx,
               float* __restrict__ out,
               int E, int estart, int N)
{
    int e = estart + blockIdx.x;
    if (e >= E) return;
    __shared__ __align__(16) float s_a[64];
    __shared__ float2 s_part[4];
    int j = threadIdx.x, lane = j & 31, warp = j >> 5;
    const bool is64 = idx_is_64(eidx, N);

    if (j < 16) ((float4*)s_a)[j] = ((const float4*)(edge_attr + (size_t)e * 64))[j];
    __syncthreads();

    float acc = bias[j];
#pragma unroll
    for (int k = 0; k < 64; k++) acc += s_a[k] * W[k * 128 + j];
    float h = fmaxf(acc, 0.0f);

    float s = h, s2 = h * h;
#pragma unroll
    for (int off = 16; off > 0; off >>= 1) {
        s  += __shfl_xor_sync(0xffffffffu, s,  off);
        s2 += __shfl_xor_sync(0xffffffffu, s2, off);
    }
    if (lane == 0) s_part[warp] = make_float2(s, s2);
    __syncthreads();

    float2 p0 = s_part[0], p1 = s_part[1], p2 = s_part[2], p3 = s_part[3];
    float sum = (p0.x + p1.x) + (p2.x + p3.x);
    float ss  = (p0.y + p1.y) + (p2.y + p3.y);
    float mu  = sum * (1.0f / 128.0f);
    float var = ss * (1.0f / 128.0f) - mu * mu;
    float rs  = rsqrtf(var + 1e-5f);
    float hn  = (h - mu) * rs * gamma[j] + beta[j];

    long long src = is64 ? eidx[e] : (long long)((const int*)eidx)[e];
    long long dst = is64 ? eidx[(size_t)E + e] : (long long)((const int*)eidx)[(size_t)E + e];
    atomicAdd(out + src * 128 + j, hn);
    atomicAdd(out + dst * 128 + j, hn);
    if (j == 0) {
        atomicAdd(&g_degree[(int)src], 1.0f);
        atomicAdd(&g_degree[(int)dst], 1.0f);
    }
}

__global__ void finalize_kernel(float4* out4, int n4) {
    int i = blockIdx.x * blockDim.x + threadIdx.x;
    if (i >= n4) return;
    int row = i >> 5;                          // 32 float4 per node row
    float inv = 1.0f / fmaxf(g_degree[row], 1.0f);
    float4 v = out4[i];
    v.x *= inv; v.y *= inv; v.z *= inv; v.w *= inv;
    out4[i] = v;
}

extern "C" void kernel_launch(void* const* d_in, const int* in_sizes, int n_in,
                              void* d_out, int out_size) {
    const float* edge_attr      = (const float*)d_in[0];
    const float* W              = (const float*)d_in[1];
    const float* b              = (const float*)d_in[2];
    const float* gamma          = (const float*)d_in[3];
    const float* beta           = (const float*)d_in[4];
    const long long* eidx       = (const long long*)d_in[5];
    float* out = (float*)d_out;

    const int E = in_sizes[0] / 64;
    const int N = out_size / 128;
    const int n4 = out_size / 4;        // N*32 float4

    zero_kernel<<<(n4 + 255) / 256, 256>>>((float4*)out, n4, N);

    const int nbatch = E / NB;
    if (nbatch > 0)
        edge2node_main<<<888, 128>>>(edge_attr, W, b, gamma, beta, eidx,
                                     out, E, nbatch, N);
    const int tail = E - nbatch * NB;
    if (tail > 0)
        edge2node_tail<<<tail, 128>>>(edge_attr, W, b, gamma, beta, eidx,
                                      out, E, nbatch * NB, N);

    finalize_kernel<<<(n4 + 255) / 256, 256>>>((float4*)out, n4);
}

// round 4
// speedup vs baseline: 1.5373x; 1.5373x over previous
#include <cuda_runtime.h>

// ---------------------------------------------------------------------------
// Edge2NodeFeatures: h = LN(relu(A @ W + b)); out[n] = (scatter_add dst + src) / deg
// A: [E,64] f32, W: [64,128] f32, edge_index: [2,E] i64 (or i32 — detected),
// out: [N,128] f32.
//
// Main kernel: 128 threads = 2 independent 64-thread groups. Each group
// processes NB=4 edges/batch; each thread owns 2 output columns (j, j+64)
// with the W columns K-packed in 128 registers for fma.rn.f32x2.
// LDS.128 broadcast of A is amortized over 4 fma2 (was 2).
// ---------------------------------------------------------------------------

#define NB 4                     // edges per batch PER GROUP (block does 2*NB)
#define DEG_CAP (1 << 20)

__device__ float g_degree[DEG_CAP];

// ---- packed f32x2 helpers (FFMA2 path; only reachable via PTX) ----
__device__ __forceinline__ unsigned long long pack2(float lo, float hi) {
    unsigned long long r;
    asm("mov.b64 %0, {%1, %2};" : "=l"(r) : "f"(lo), "f"(hi));
    return r;
}
__device__ __forceinline__ unsigned long long fma2(unsigned long long a,
                                                   unsigned long long w,
                                                   unsigned long long c) {
    unsigned long long d;
    asm("fma.rn.f32x2 %0, %1, %2, %3;" : "=l"(d) : "l"(a), "l"(w), "l"(c));
    return d;
}
__device__ __forceinline__ float2 unpack2(unsigned long long v) {
    unsigned int lo, hi;
    asm("mov.b64 {%0, %1}, %2;" : "=r"(lo), "=r"(hi) : "l"(v));
    return make_float2(__uint_as_float(lo), __uint_as_float(hi));
}

// Detect whether edge_index is int64 or int32 (JAX x64-off downcast).
__device__ __forceinline__ bool idx_is_64(const long long* eidx, int N) {
    bool ok = true;
#pragma unroll
    for (int t = 0; t < 4; t++) {
        unsigned long long v = (unsigned long long)eidx[t];
        if (v >= (unsigned long long)N) ok = false;
    }
    return ok;
}

__global__ void zero_kernel(float4* out4, int n4, int N) {
    int i = blockIdx.x * blockDim.x + threadIdx.x;
    if (i < n4) out4[i] = make_float4(0.f, 0.f, 0.f, 0.f);
    if (i < N)  g_degree[i] = 0.f;
}

// ---------------------------------------------------------------------------
// Main fused kernel.
// ---------------------------------------------------------------------------
__global__ void __launch_bounds__(128)
edge2node_main(const float* __restrict__ edge_attr,
               const float* __restrict__ W,
               const float* __restrict__ bias,
               const float* __restrict__ gamma,
               const float* __restrict__ beta,
               const long long* __restrict__ eidx,
               float* __restrict__ out,
               int E, int nbb, int N)
{
    __shared__ __align__(16) float s_a[2][NB * 64];    // staged A rows per group
    __shared__ __align__(16) float s_h[2][NB * 128];   // normalized h per group
    __shared__ float2 s_part[2][2][NB];                // per-group per-warp (sum,ss)
    __shared__ long long s_idx[2][2 * NB];             // per-group [src x NB, dst x NB]

    const int tid  = threadIdx.x;
    const int grp  = tid >> 6;          // 0 or 1: which 64-thread group
    const int t    = tid & 63;          // thread within group; owns cols t, t+64
    const int lane = tid & 31;
    const int wig  = (tid >> 5) & 1;    // warp within group
    const int j0 = t, j1 = t + 64;
    const bool is64 = idx_is_64(eidx, N);

    // W columns j0 and j1, K-packed into (k,k+1) f32x2 pairs: 2 x 32 ull = 128 regs
    unsigned long long wA[32], wB[32];
#pragma unroll
    for (int kk = 0; kk < 32; kk++) {
        wA[kk] = pack2(W[(2 * kk) * 128 + j0], W[(2 * kk + 1) * 128 + j0]);
        wB[kk] = pack2(W[(2 * kk) * 128 + j1], W[(2 * kk + 1) * 128 + j1]);
    }
    const float b0 = bias[j0],  b1 = bias[j1];
    const float g0 = gamma[j0], g1 = gamma[j1];
    const float t0 = beta[j0],  t1 = beta[j1];

    for (int bb = blockIdx.x; bb < nbb; bb += (int)gridDim.x) {
        const int e0 = bb * (2 * NB) + grp * NB;     // this group's 4 edges

        // stage A: NB*64 floats = 64 float4, one per thread in the group
        ((float4*)s_a[grp])[t] =
            ((const float4*)(edge_attr + (size_t)e0 * 64))[t];
        if (t < NB) {
            s_idx[grp][t] = is64 ? eidx[e0 + t]
                                 : (long long)((const int*)eidx)[e0 + t];
            s_idx[grp][NB + t] = is64 ? eidx[(size_t)E + e0 + t]
                                      : (long long)((const int*)eidx)[(size_t)E + e0 + t];
        }
        __syncthreads();

        // GEMM mainloop: per kk4 per edge: 1 broadcast LDS.128 -> 4 fma2
        unsigned long long acc0[NB], acc1[NB];       // col j0 / col j1
#pragma unroll
        for (int m = 0; m < NB; m++) { acc0[m] = 0ull; acc1[m] = 0ull; }

#pragma unroll
        for (int kk4 = 0; kk4 < 16; kk4++) {
#pragma unroll
            for (int m = 0; m < NB; m++) {
                const ulonglong2 av =
                    *(const ulonglong2*)(s_a[grp] + m * 64 + kk4 * 4);
                acc0[m] = fma2(av.y, wA[2 * kk4 + 1], fma2(av.x, wA[2 * kk4], acc0[m]));
                acc1[m] = fma2(av.y, wB[2 * kk4 + 1], fma2(av.x, wB[2 * kk4], acc1[m]));
            }
        }

        float h0[NB], h1[NB];
#pragma unroll
        for (int m = 0; m < NB; m++) {
            float2 a = unpack2(acc0[m]);
            float2 b = unpack2(acc1[m]);
            h0[m] = fmaxf(a.x + a.y + b0, 0.0f);
            h1[m] = fmaxf(b.x + b.y + b1, 0.0f);
        }

        // LN reduction: per-thread local (2 cols) -> warp butterfly -> 2 warps
#pragma unroll
        for (int m = 0; m < NB; m++) {
            float s  = h0[m] + h1[m];
            float s2 = h0[m] * h0[m] + h1[m] * h1[m];
#pragma unroll
            for (int off = 16; off > 0; off >>= 1) {
                s  += __shfl_xor_sync(0xffffffffu, s,  off);
                s2 += __shfl_xor_sync(0xffffffffu, s2, off);
            }
            if (lane == 0) s_part[grp][wig][m] = make_float2(s, s2);
        }
        __syncthreads();

#pragma unroll
        for (int m = 0; m < NB; m++) {
            float2 p0 = s_part[grp][0][m], p1 = s_part[grp][1][m];
            float sum = p0.x + p1.x;
            float ss  = p0.y + p1.y;
            float mu  = sum * (1.0f / 128.0f);
            float var = ss * (1.0f / 128.0f) - mu * mu;
            float rs  = rsqrtf(var + 1e-5f);
            s_h[grp][m * 128 + j0] = (h0[m] - mu) * rs * g0 + t0;
            s_h[grp][m * 128 + j1] = (h1[m] - mu) * rs * g1 + t1;
        }
        __syncthreads();

        // scatter: NB edges x {src,dst} x 32 quads = 256 red.v4 over 64 threads
#pragma unroll
        for (int r = 0; r < 4; r++) {
            int item = t + 64 * r;            // 0..255
            int m    = item >> 6;             // edge within batch
            int sg   = (item >> 5) & 1;       // 0=src, 1=dst
            int q    = item & 31;             // float4 quad within 128 cols
            long long node = s_idx[grp][sg * NB + m];
            float4 v = ((const float4*)(s_h[grp] + m * 128))[q];
            float* p = out + node * 128 + q * 4;
            asm volatile("red.global.add.v4.f32 [%0], {%1,%2,%3,%4};"
                         :: "l"(p), "f"(v.x), "f"(v.y), "f"(v.z), "f"(v.w)
                         : "memory");
        }
        if (t < 2 * NB) atomicAdd(&g_degree[(int)s_idx[grp][t]], 1.0f);
        __syncthreads();
    }
}

// Slow path for E % (2*NB) tail edges (one block per edge).
__global__ void __launch_bounds__(128)
edge2node_tail(const float* __restrict__ edge_attr,
               const float* __restrict__ W,
               const float* __restrict__ bias,
               const float* __restrict__ gamma,
               const float* __restrict__ beta,
               const long long* __restrict__ eidx,
               float* __restrict__ out,
               int E, int estart, int N)
{
    int e = estart + blockIdx.x;
    if (e >= E) return;
    __shared__ __align__(16) float s_a[64];
    __shared__ float2 s_part[4];
    int j = threadIdx.x, lane = j & 31, warp = j >> 5;
    const bool is64 = idx_is_64(eidx, N);

    if (j < 16) ((float4*)s_a)[j] = ((const float4*)(edge_attr + (size_t)e * 64))[j];
    __syncthreads();

    float acc = bias[j];
#pragma unroll
    for (int k = 0; k < 64; k++) acc += s_a[k] * W[k * 128 + j];
    float h = fmaxf(acc, 0.0f);

    float s = h, s2 = h * h;
#pragma unroll
    for (int off = 16; off > 0; off >>= 1) {
        s  += __shfl_xor_sync(0xffffffffu, s,  off);
        s2 += __shfl_xor_sync(0xffffffffu, s2, off);
    }
    if (lane == 0) s_part[warp] = make_float2(s, s2);
    __syncthreads();

    float2 p0 = s_part[0], p1 = s_part[1], p2 = s_part[2], p3 = s_part[3];
    float sum = (p0.x + p1.x) + (p2.x + p3.x);
    float ss  = (p0.y + p1.y) + (p2.y + p3.y);
    float mu  = sum * (1.0f / 128.0f);
    float var = ss * (1.0f / 128.0f) - mu * mu;
    float rs  = rsqrtf(var + 1e-5f);
    float hn  = (h - mu) * rs * gamma[j] + beta[j];

    long long src = is64 ? eidx[e] : (long long)((const int*)eidx)[e];
    long long dst = is64 ? eidx[(size_t)E + e] : (long long)((const int*)eidx)[(size_t)E + e];
    atomicAdd(out + src * 128 + j, hn);
    atomicAdd(out + dst * 128 + j, hn);
    if (j == 0) {
        atomicAdd(&g_degree[(int)src], 1.0f);
        atomicAdd(&g_degree[(int)dst], 1.0f);
    }
}

__global__ void finalize_kernel(float4* out4, int n4) {
    int i = blockIdx.x * blockDim.x + threadIdx.x;
    if (i >= n4) return;
    int row = i >> 5;                          // 32 float4 per node row
    float inv = 1.0f / fmaxf(g_degree[row], 1.0f);
    float4 v = out4[i];
    v.x *= inv; v.y *= inv; v.z *= inv; v.w *= inv;
    out4[i] = v;
}

extern "C" void kernel_launch(void* const* d_in, const int* in_sizes, int n_in,
                              void* d_out, int out_size) {
    const float* edge_attr      = (const float*)d_in[0];
    const float* W              = (const float*)d_in[1];
    const float* b              = (const float*)d_in[2];
    const float* gamma          = (const float*)d_in[3];
    const float* beta           = (const float*)d_in[4];
    const long long* eidx       = (const long long*)d_in[5];
    float* out = (float*)d_out;

    const int E = in_sizes[0] / 64;
    const int N = out_size / 128;
    const int n4 = out_size / 4;        // N*32 float4

    zero_kernel<<<(n4 + 255) / 256, 256>>>((float4*)out, n4, N);

    const int per_block = 2 * NB;
    const int nbb = E / per_block;
    if (nbb > 0)
        edge2node_main<<<592, 128>>>(edge_attr, W, b, gamma, beta, eidx,
                                     out, E, nbb, N);
    const int tail = E - nbb * per_block;
    if (tail > 0)
        edge2node_tail<<<tail, 128>>>(edge_attr, W, b, gamma, beta, eidx,
                                      out, E, nbb * per_block, N);

    finalize_kernel<<<(n4 + 255) / 256, 256>>>((float4*)out, n4);
}

// round 7
// speedup vs baseline: 3.3648x; 2.1887x over previous
#include <cuda_runtime.h>
#include <cuda_bf16.h>
#include <cstdint>

// ---------------------------------------------------------------------------
// Edge2NodeFeatures via mma.sync (baseline-PTX HMMA, bf16 split x3 products):
//   h = LN(relu(A @ W + b)); out[n] = (scatter_add over src/dst of h) / deg
// A: [E,64] f32, W: [64,128] f32, edge_index: [2,E] i64/i32 (detected).
// Persistent kernel: 1 CTA/SM, 256 threads, tile = 128 edges x 128 cols.
// ---------------------------------------------------------------------------

#define DEG_CAP (1 << 20)
__device__ float g_degree[DEG_CAP];

#define SWZ128(b) ((b) ^ (((b) >> 3) & 0x70))

// ---------------- SMEM layout (dynamic) ----------------
#define OFF_W_HI 0          // 128 n-rows x 128B (64 bf16 k)  = 16384
#define OFF_W_LO 16384
#define OFF_A_HI 32768      // 128 m-rows x 128B              = 16384
#define OFF_A_LO 49152
#define OFF_SH   65536      // 128 rows x 528B (132 f32 pad)  = 67584
#define OFF_PART 133120     // 128 rows x 2 warps x float2    = 2048
#define OFF_SRC  135168     // 128 x i32
#define OFF_DST  135680     // 128 x i32
#define SMEM_TOTAL 136192

__device__ __forceinline__ uint32_t smem_u32(const void* p) {
    uint32_t a;
    asm("{ .reg .u64 t; cvta.to.shared.u64 t, %1; cvt.u32.u64 %0, t; }"
        : "=r"(a) : "l"(p));
    return a;
}

__device__ __forceinline__ void ldsm_x4(uint32_t addr, uint32_t& r0, uint32_t& r1,
                                        uint32_t& r2, uint32_t& r3) {
    asm volatile("ldmatrix.sync.aligned.m8n8.x4.shared.b16 {%0,%1,%2,%3}, [%4];"
                 : "=r"(r0), "=r"(r1), "=r"(r2), "=r"(r3) : "r"(addr));
}

__device__ __forceinline__ void mma16816(float* c,
                                         uint32_t a0, uint32_t a1, uint32_t a2, uint32_t a3,
                                         uint32_t b0, uint32_t b1) {
    asm volatile("mma.sync.aligned.m16n8k16.row.col.f32.bf16.bf16.f32 "
                 "{%0,%1,%2,%3}, {%4,%5,%6,%7}, {%8,%9}, {%0,%1,%2,%3};"
                 : "+f"(c[0]), "+f"(c[1]), "+f"(c[2]), "+f"(c[3])
                 : "r"(a0), "r"(a1), "r"(a2), "r"(a3), "r"(b0), "r"(b1));
}

__device__ __forceinline__ bool idx_is_64(const long long* eidx, int N) {
    bool ok = true;
#pragma unroll
    for (int t = 0; t < 4; t++)
        if ((unsigned long long)eidx[t] >= (unsigned long long)N) ok = false;
    return ok;
}

__global__ void zero_kernel(float4* out4, int n4, int N) {
    int i = blockIdx.x * blockDim.x + threadIdx.x;
    if (i < n4) out4[i] = make_float4(0.f, 0.f, 0.f, 0.f);
    if (i < N)  g_degree[i] = 0.f;
}

// One GEMM product pass: C += A_buf(128x64 bf16) @ W_buf(64x128 bf16)^T-stored
__device__ __forceinline__ void product_pass(uint32_t saA, uint32_t saW,
                                             const uint32_t* rowoff_a,   // [2]
                                             const uint32_t* rowoff_b,   // [4]
                                             float c[2][8][4]) {
#pragma unroll
    for (int ks = 0; ks < 4; ks++) {
        uint32_t a[2][4];
#pragma unroll
        for (int mi = 0; mi < 2; mi++)
            ldsm_x4(saA + SWZ128(rowoff_a[mi] + ks * 32),
                    a[mi][0], a[mi][1], a[mi][2], a[mi][3]);
        uint32_t b[4][4];
#pragma unroll
        for (int bt = 0; bt < 4; bt++)
            ldsm_x4(saW + SWZ128(rowoff_b[bt] + ks * 32),
                    b[bt][0], b[bt][1], b[bt][2], b[bt][3]);
#pragma unroll
        for (int mi = 0; mi < 2; mi++)
#pragma unroll
            for (int ni = 0; ni < 8; ni++)
                mma16816(c[mi][ni], a[mi][0], a[mi][1], a[mi][2], a[mi][3],
                         b[ni >> 1][(ni & 1) * 2], b[ni >> 1][(ni & 1) * 2 + 1]);
    }
}

// ---------------------------------------------------------------------------
__global__ void __launch_bounds__(256, 1)
edge2node_mma(const float* __restrict__ edge_attr,
              const float* __restrict__ W,
              const float* __restrict__ bias,
              const float* __restrict__ gamma,
              const float* __restrict__ beta,
              const long long* __restrict__ eidx,
              float* __restrict__ out,
              int E, int ntiles, int Nn)
{
    extern __shared__ __align__(1024) char smem[];
    const uint32_t sa = smem_u32(smem);
    const int tid = threadIdx.x, wid = tid >> 5, lane = tid & 31;
    const int mw = wid & 3, nw = wid >> 2;          // warp tile coords
    const int Mb = mw * 32, Nb = nw * 64;
    const bool is64 = idx_is_64(eidx, Nn);

    // ---- one-time W split preload: W[k][n] f32 -> [n][k] bf16 hi/lo, SW128 ----
    for (int idx = tid; idx < 64 * 128; idx += 256) {
        int k = idx >> 7, n = idx & 127;
        float w = W[idx];
        __nv_bfloat16 hi = __float2bfloat16(w);
        float lo = w - __bfloat162float(hi);
        uint32_t sw = SWZ128((uint32_t)(n * 128 + k * 2));
        *(unsigned short*)(smem + OFF_W_HI + sw) = __bfloat16_as_ushort(hi);
        *(unsigned short*)(smem + OFF_W_LO + sw) = __bfloat16_as_ushort(__float2bfloat16(lo));
    }

    // ---- per-thread column params (cols fixed per thread) ----
    float pb[16], pg[16], pt[16];
#pragma unroll
    for (int ni = 0; ni < 8; ni++)
#pragma unroll
        for (int h = 0; h < 2; h++) {
            int col = Nb + ni * 8 + (lane & 3) * 2 + h;
            pb[ni * 2 + h] = bias[col];
            pg[ni * 2 + h] = gamma[col];
            pt[ni * 2 + h] = beta[col];
        }

    // ---- ldmatrix lane row-offsets (bytes within buffer, pre-swizzle) ----
    const int grp = lane >> 3, r8 = lane & 7;
    uint32_t rowoff_a[2], rowoff_b[4];
#pragma unroll
    for (int mi = 0; mi < 2; mi++)
        rowoff_a[mi] = (uint32_t)((Mb + mi * 16 + (grp & 1) * 8 + r8) * 128 + (grp >> 1) * 16);
#pragma unroll
    for (int bt = 0; bt < 4; bt++)
        rowoff_b[bt] = (uint32_t)((Nb + bt * 16 + (grp >> 1) * 8 + r8) * 128 + (grp & 1) * 16);

    __syncthreads();

    for (int tile = blockIdx.x; tile < ntiles; tile += (int)gridDim.x) {
        const int base_e = tile * 128;

        // ---- stage edge indices + degree ----
        if (tid < 128) {
            int e = base_e + tid;
            int sv = 0, dv = 0;
            if (e < E) {
                sv = is64 ? (int)eidx[e] : ((const int*)eidx)[e];
                dv = is64 ? (int)eidx[(size_t)E + e] : ((const int*)eidx)[(size_t)E + e];
                atomicAdd(&g_degree[sv], 1.0f);
                atomicAdd(&g_degree[dv], 1.0f);
            }
            ((int*)(smem + OFF_SRC))[tid] = sv;
            ((int*)(smem + OFF_DST))[tid] = dv;
        }

        // ---- load A tile, split bf16 hi/lo, store swizzled ----
        const float4* Ap = (const float4*)edge_attr + (size_t)base_e * 16;
#pragma unroll
        for (int u = 0; u < 8; u++) {
            int idx = tid + u * 256;               // 2048 float4 in tile
            int row = idx >> 4, c4 = idx & 15;
            float4 a = make_float4(0.f, 0.f, 0.f, 0.f);
            if (base_e + row < E) a = Ap[idx];
            __nv_bfloat16 h0 = __float2bfloat16(a.x), h1 = __float2bfloat16(a.y);
            __nv_bfloat16 h2 = __float2bfloat16(a.z), h3 = __float2bfloat16(a.w);
            float l0 = a.x - __bfloat162float(h0), l1 = a.y - __bfloat162float(h1);
            float l2 = a.z - __bfloat162float(h2), l3 = a.w - __bfloat162float(h3);
            uint32_t hi01 = ((uint32_t)__bfloat16_as_ushort(h1) << 16) | __bfloat16_as_ushort(h0);
            uint32_t hi23 = ((uint32_t)__bfloat16_as_ushort(h3) << 16) | __bfloat16_as_ushort(h2);
            uint32_t lo01 = ((uint32_t)__bfloat16_as_ushort(__float2bfloat16(l1)) << 16)
                          | __bfloat16_as_ushort(__float2bfloat16(l0));
            uint32_t lo23 = ((uint32_t)__bfloat16_as_ushort(__float2bfloat16(l3)) << 16)
                          | __bfloat16_as_ushort(__float2bfloat16(l2));
            uint32_t sw = SWZ128((uint32_t)(row * 128 + c4 * 8));
            *(uint2*)(smem + OFF_A_HI + sw) = make_uint2(hi01, hi23);
            *(uint2*)(smem + OFF_A_LO + sw) = make_uint2(lo01, lo23);
        }
        __syncthreads();

        // ---- GEMM: c = bias; c += Ahi@Whi + Ahi@Wlo + Alo@Whi ----
        float c[2][8][4];
#pragma unroll
        for (int mi = 0; mi < 2; mi++)
#pragma unroll
            for (int ni = 0; ni < 8; ni++)
#pragma unroll
                for (int rr = 0; rr < 4; rr++)
                    c[mi][ni][rr] = pb[ni * 2 + (rr & 1)];

        product_pass(sa + OFF_A_HI, sa + OFF_W_HI, rowoff_a, rowoff_b, c);
        product_pass(sa + OFF_A_HI, sa + OFF_W_LO, rowoff_a, rowoff_b, c);
        product_pass(sa + OFF_A_LO, sa + OFF_W_HI, rowoff_a, rowoff_b, c);

        // ---- relu + per-row stats (4 rows/thread) ----
        float sm[4] = {0.f, 0.f, 0.f, 0.f}, sq[4] = {0.f, 0.f, 0.f, 0.f};
#pragma unroll
        for (int mi = 0; mi < 2; mi++)
#pragma unroll
            for (int ni = 0; ni < 8; ni++)
#pragma unroll
                for (int rr = 0; rr < 4; rr++) {
                    float h = fmaxf(c[mi][ni][rr], 0.f);
                    c[mi][ni][rr] = h;
                    int slot = mi * 2 + (rr >> 1);
                    sm[slot] += h;
                    sq[slot] = fmaf(h, h, sq[slot]);
                }
#pragma unroll
        for (int slot = 0; slot < 4; slot++) {
            sm[slot] += __shfl_xor_sync(0xffffffffu, sm[slot], 1);
            sq[slot] += __shfl_xor_sync(0xffffffffu, sq[slot], 1);
            sm[slot] += __shfl_xor_sync(0xffffffffu, sm[slot], 2);
            sq[slot] += __shfl_xor_sync(0xffffffffu, sq[slot], 2);
        }
        if ((lane & 3) == 0) {
#pragma unroll
            for (int slot = 0; slot < 4; slot++) {
                int row = Mb + (slot >> 1) * 16 + (slot & 1) * 8 + (lane >> 2);
                *(float2*)(smem + OFF_PART + (row * 2 + nw) * 8) = make_float2(sm[slot], sq[slot]);
            }
        }
        __syncthreads();

        // ---- combine halves, normalize, stage ----
        float mu[4], rs[4];
#pragma unroll
        for (int slot = 0; slot < 4; slot++) {
            int row = Mb + (slot >> 1) * 16 + (slot & 1) * 8 + (lane >> 2);
            float2 p0 = *(const float2*)(smem + OFF_PART + (row * 2 + 0) * 8);
            float2 p1 = *(const float2*)(smem + OFF_PART + (row * 2 + 1) * 8);
            float sum = p0.x + p1.x, ss = p0.y + p1.y;
            mu[slot] = sum * (1.0f / 128.0f);
            float var = ss * (1.0f / 128.0f) - mu[slot] * mu[slot];
            rs[slot] = rsqrtf(var + 1e-5f);
        }
#pragma unroll
        for (int mi = 0; mi < 2; mi++)
#pragma unroll
            for (int rh = 0; rh < 2; rh++) {
                int slot = mi * 2 + rh;
                int row = Mb + mi * 16 + rh * 8 + (lane >> 2);
                char* rp = smem + OFF_SH + row * 528;
#pragma unroll
                for (int ni = 0; ni < 8; ni++) {
                    float y0 = (c[mi][ni][rh * 2 + 0] - mu[slot]) * rs[slot] * pg[ni * 2 + 0] + pt[ni * 2 + 0];
                    float y1 = (c[mi][ni][rh * 2 + 1] - mu[slot]) * rs[slot] * pg[ni * 2 + 1] + pt[ni * 2 + 1];
                    *(float2*)(rp + (Nb + ni * 8 + (lane & 3) * 2) * 4) = make_float2(y0, y1);
                }
            }
        __syncthreads();

        // ---- scatter: 2 endpoints x 128 edges x 32 quads = 8192 red.v4 ----
#pragma unroll 8
        for (int r2 = 0; r2 < 32; r2++) {
            int item = tid + 256 * r2;
            int q = item & 31;                  // = lane
            int rowsel = item >> 5;             // 0..255
            int ep = rowsel >> 7, m = rowsel & 127;
            if (base_e + m < E) {
                int node = ((const int*)(smem + (ep ? OFF_DST : OFF_SRC)))[m];
                float4 v = *(const float4*)(smem + OFF_SH + m * 528 + q * 16);
                float* p = out + (size_t)node * 128 + q * 4;
                asm volatile("red.global.add.v4.f32 [%0], {%1,%2,%3,%4};"
                             :: "l"(p), "f"(v.x), "f"(v.y), "f"(v.z), "f"(v.w)
                             : "memory");
            }
        }
        __syncthreads();
    }
}

__global__ void finalize_kernel(float4* out4, int n4) {
    int i = blockIdx.x * blockDim.x + threadIdx.x;
    if (i >= n4) return;
    int row = i >> 5;
    float inv = 1.0f / fmaxf(g_degree[row], 1.0f);
    float4 v = out4[i];
    v.x *= inv; v.y *= inv; v.z *= inv; v.w *= inv;
    out4[i] = v;
}

extern "C" void kernel_launch(void* const* d_in, const int* in_sizes, int n_in,
                              void* d_out, int out_size) {
    const float* edge_attr = (const float*)d_in[0];
    const float* W         = (const float*)d_in[1];
    const float* b         = (const float*)d_in[2];
    const float* gamma     = (const float*)d_in[3];
    const float* beta      = (const float*)d_in[4];
    const long long* eidx  = (const long long*)d_in[5];
    float* out = (float*)d_out;

    const int E  = in_sizes[0] / 64;
    const int N  = out_size / 128;
    const int n4 = out_size / 4;

    cudaFuncSetAttribute(edge2node_mma, cudaFuncAttributeMaxDynamicSharedMemorySize,
                         SMEM_TOTAL);

    zero_kernel<<<(n4 + 255) / 256, 256>>>((float4*)out, n4, N);

    const int ntiles = (E + 127) / 128;
    edge2node_mma<<<152, 256, SMEM_TOTAL>>>(edge_attr, W, b, gamma, beta, eidx,
                                            out, E, ntiles, N);

    finalize_kernel<<<(n4 + 255) / 256, 256>>>((float4*)out, n4);
}

// round 8
// speedup vs baseline: 3.9648x; 1.1783x over previous
#include <cuda_runtime.h>
#include <cuda_bf16.h>
#include <cstdint>

// ---------------------------------------------------------------------------
// Edge2NodeFeatures via mma.sync (baseline-PTX HMMA, bf16 split x3 products):
//   h = LN(relu(A @ W + b)); out[n] = (scatter_add over src/dst of h) / deg
// Fused persistent kernel: GEMM+LN+scatter phase, grid barrier, finalize.
// ---------------------------------------------------------------------------

#define DEG_CAP (1 << 20)
__device__ float g_degree[DEG_CAP];
__device__ unsigned g_bar_count;
__device__ unsigned g_bar_sense;

#define SWZ128(b) ((b) ^ (((b) >> 3) & 0x70))

// ---------------- SMEM layout (dynamic) ----------------
#define OFF_W_LO 0          // 128 n-rows x 128B                = 16384
#define OFF_A_HI 16384      // 128 m-rows x 128B                = 16384
#define OFF_A_LO 32768
#define OFF_SH   49152      // 128 rows x 528B (132 f32 pad)    = 67584
#define OFF_W_HI OFF_SH     // aliased: W_HI only lives in setup
#define OFF_PART 116736     // 128 rows x 2 x float2            = 2048
#define OFF_SRC  118784     // 128 x i32
#define OFF_DST  119296
#define OFF_PRM  119808     // bias[128], gamma[128], beta[128] = 1536
#define SMEM_TOTAL 121344

__device__ __forceinline__ uint32_t smem_u32(const void* p) {
    uint32_t a;
    asm("{ .reg .u64 t; cvta.to.shared.u64 t, %1; cvt.u32.u64 %0, t; }"
        : "=r"(a) : "l"(p));
    return a;
}

__device__ __forceinline__ void ldsm_x4(uint32_t addr, uint32_t& r0, uint32_t& r1,
                                        uint32_t& r2, uint32_t& r3) {
    asm volatile("ldmatrix.sync.aligned.m8n8.x4.shared.b16 {%0,%1,%2,%3}, [%4];"
                 : "=r"(r0), "=r"(r1), "=r"(r2), "=r"(r3) : "r"(addr));
}

__device__ __forceinline__ void mma16816(float* c,
                                         uint32_t a0, uint32_t a1, uint32_t a2, uint32_t a3,
                                         uint32_t b0, uint32_t b1) {
    asm volatile("mma.sync.aligned.m16n8k16.row.col.f32.bf16.bf16.f32 "
                 "{%0,%1,%2,%3}, {%4,%5,%6,%7}, {%8,%9}, {%0,%1,%2,%3};"
                 : "+f"(c[0]), "+f"(c[1]), "+f"(c[2]), "+f"(c[3])
                 : "r"(a0), "r"(a1), "r"(a2), "r"(a3), "r"(b0), "r"(b1));
}

__device__ __forceinline__ bool idx_is_64(const long long* eidx, int N) {
    bool ok = true;
#pragma unroll
    for (int t = 0; t < 4; t++)
        if ((unsigned long long)eidx[t] >= (unsigned long long)N) ok = false;
    return ok;
}

__global__ void zero_kernel(float4* out4, int n4, int N) {
    int i = blockIdx.x * blockDim.x + threadIdx.x;
    if (i < n4) out4[i] = make_float4(0.f, 0.f, 0.f, 0.f);
    if (i < N)  g_degree[i] = 0.f;
}

// ---------------------------------------------------------------------------
__global__ void __launch_bounds__(256, 1)
edge2node_fused(const float* __restrict__ edge_attr,
                const float* __restrict__ W,
                const float* __restrict__ bias,
                const float* __restrict__ gamma,
                const float* __restrict__ beta,
                const long long* __restrict__ eidx,
                float* __restrict__ out,
                int E, int ntiles, int Nn)
{
    extern __shared__ __align__(1024) char smem[];
    const uint32_t sa = smem_u32(smem);
    const int tid = threadIdx.x, wid = tid >> 5, lane = tid & 31;
    const int mw = wid & 3, nw = wid >> 2;
    const int Mb = mw * 32, Nb = nw * 64;
    const bool is64 = idx_is_64(eidx, Nn);
    const int step = (int)gridDim.x;

    // ---- setup: W split into W_HI (aliased w/ SH) and W_LO, params table ----
    for (int idx = tid; idx < 64 * 128; idx += 256) {
        int k = idx >> 7, n = idx & 127;
        float w = W[idx];
        __nv_bfloat16 hi = __float2bfloat16(w);
        float lo = w - __bfloat162float(hi);
        uint32_t sw = SWZ128((uint32_t)(n * 128 + k * 2));
        *(unsigned short*)(smem + OFF_W_HI + sw) = __bfloat16_as_ushort(hi);
        *(unsigned short*)(smem + OFF_W_LO + sw) = __bfloat16_as_ushort(__float2bfloat16(lo));
    }
    if (tid < 128) {
        ((float*)(smem + OFF_PRM))[tid]       = bias[tid];
        ((float*)(smem + OFF_PRM + 512))[tid] = gamma[tid];
        ((float*)(smem + OFF_PRM + 1024))[tid] = beta[tid];
    }

    // ldmatrix lane row-offsets (bytes, pre-swizzle)
    const int grp = lane >> 3, r8 = lane & 7;
    uint32_t rowoff_a[2], rowoff_b[4];
#pragma unroll
    for (int mi = 0; mi < 2; mi++)
        rowoff_a[mi] = (uint32_t)((Mb + mi * 16 + (grp & 1) * 8 + r8) * 128 + (grp >> 1) * 16);
#pragma unroll
    for (int bt = 0; bt < 4; bt++)
        rowoff_b[bt] = (uint32_t)((Nb + bt * 16 + (grp >> 1) * 8 + r8) * 128 + (grp & 1) * 16);

    __syncthreads();

    // ---- hoist W_HI fragments (tile-invariant): 4 ks x 4 bt x 4 regs ----
    uint32_t bhi[4][4][4];
#pragma unroll
    for (int ks = 0; ks < 4; ks++)
#pragma unroll
        for (int bt = 0; bt < 4; bt++)
            ldsm_x4(sa + OFF_W_HI + SWZ128(rowoff_b[bt] + ks * 32),
                    bhi[ks][bt][0], bhi[ks][bt][1], bhi[ks][bt][2], bhi[ks][bt][3]);

    // ---- per-thread bias (8 float2, cols fixed per thread) ----
    float2 bb[8];
#pragma unroll
    for (int ni = 0; ni < 8; ni++)
        bb[ni] = *(const float2*)(smem + OFF_PRM + (Nb + ni * 8 + (lane & 3) * 2) * 4);

    // ---- prefetch first tile ----
    float4 pref[8];
    int ps = 0, pd = 0;
    int tile = blockIdx.x;
    if (tile < ntiles) {
        const float4* Ap = (const float4*)edge_attr + (size_t)tile * 128 * 16;
#pragma unroll
        for (int u = 0; u < 8; u++) {
            int idx = tid + u * 256, row = idx >> 4;
            pref[u] = (tile * 128 + row < E) ? Ap[idx] : make_float4(0.f, 0.f, 0.f, 0.f);
        }
        if (tid < 128 && tile * 128 + tid < E) {
            int e = tile * 128 + tid;
            ps = is64 ? (int)eidx[e] : ((const int*)eidx)[e];
            pd = is64 ? (int)eidx[(size_t)E + e] : ((const int*)eidx)[(size_t)E + e];
        }
    }
    __syncthreads();   // W_HI consumed; SH region free for staging

    // =======================  main loop  =======================
    while (tile < ntiles) {
        const int base_e = tile * 128;

        // ---- store staged A (split bf16 hi/lo, SW128) + indices + degree ----
#pragma unroll
        for (int u = 0; u < 8; u++) {
            int idx = tid + u * 256, row = idx >> 4, c4 = idx & 15;
            float4 a = pref[u];
            __nv_bfloat16 h0 = __float2bfloat16(a.x), h1 = __float2bfloat16(a.y);
            __nv_bfloat16 h2 = __float2bfloat16(a.z), h3 = __float2bfloat16(a.w);
            float l0 = a.x - __bfloat162float(h0), l1 = a.y - __bfloat162float(h1);
            float l2 = a.z - __bfloat162float(h2), l3 = a.w - __bfloat162float(h3);
            uint32_t hi01 = ((uint32_t)__bfloat16_as_ushort(h1) << 16) | __bfloat16_as_ushort(h0);
            uint32_t hi23 = ((uint32_t)__bfloat16_as_ushort(h3) << 16) | __bfloat16_as_ushort(h2);
            uint32_t lo01 = ((uint32_t)__bfloat16_as_ushort(__float2bfloat16(l1)) << 16)
                          | __bfloat16_as_ushort(__float2bfloat16(l0));
            uint32_t lo23 = ((uint32_t)__bfloat16_as_ushort(__float2bfloat16(l3)) << 16)
                          | __bfloat16_as_ushort(__float2bfloat16(l2));
            uint32_t sw = SWZ128((uint32_t)(row * 128 + c4 * 8));
            *(uint2*)(smem + OFF_A_HI + sw) = make_uint2(hi01, hi23);
            *(uint2*)(smem + OFF_A_LO + sw) = make_uint2(lo01, lo23);
        }
        if (tid < 128) {
            ((int*)(smem + OFF_SRC))[tid] = ps;
            ((int*)(smem + OFF_DST))[tid] = pd;
            if (base_e + tid < E) {
                atomicAdd(&g_degree[ps], 1.0f);
                atomicAdd(&g_degree[pd], 1.0f);
            }
        }
        __syncthreads();   // S1

        // ---- prefetch next tile (hidden under GEMM) ----
        const int next = tile + step;
        if (next < ntiles) {
            const float4* Ap = (const float4*)edge_attr + (size_t)next * 128 * 16;
#pragma unroll
            for (int u = 0; u < 8; u++) {
                int idx = tid + u * 256, row = idx >> 4;
                pref[u] = (next * 128 + row < E) ? Ap[idx] : make_float4(0.f, 0.f, 0.f, 0.f);
            }
            if (tid < 128 && next * 128 + tid < E) {
                int e = next * 128 + tid;
                ps = is64 ? (int)eidx[e] : ((const int*)eidx)[e];
                pd = is64 ? (int)eidx[(size_t)E + e] : ((const int*)eidx)[(size_t)E + e];
            }
        }

        // ---- GEMM: c = bias; c += Ahi@Whi + Ahi@Wlo + Alo@Whi ----
        float c[2][8][4];
#pragma unroll
        for (int mi = 0; mi < 2; mi++)
#pragma unroll
            for (int ni = 0; ni < 8; ni++)
#pragma unroll
                for (int rr = 0; rr < 4; rr++)
                    c[mi][ni][rr] = (rr & 1) ? bb[ni].y : bb[ni].x;

#pragma unroll
        for (int ks = 0; ks < 4; ks++) {
            uint32_t aH[2][4], aL[2][4], bL[4][4];
#pragma unroll
            for (int mi = 0; mi < 2; mi++) {
                ldsm_x4(sa + OFF_A_HI + SWZ128(rowoff_a[mi] + ks * 32),
                        aH[mi][0], aH[mi][1], aH[mi][2], aH[mi][3]);
                ldsm_x4(sa + OFF_A_LO + SWZ128(rowoff_a[mi] + ks * 32),
                        aL[mi][0], aL[mi][1], aL[mi][2], aL[mi][3]);
            }
#pragma unroll
            for (int bt = 0; bt < 4; bt++)
                ldsm_x4(sa + OFF_W_LO + SWZ128(rowoff_b[bt] + ks * 32),
                        bL[bt][0], bL[bt][1], bL[bt][2], bL[bt][3]);
#pragma unroll
            for (int mi = 0; mi < 2; mi++)
#pragma unroll
                for (int ni = 0; ni < 8; ni++) {
                    const int bt = ni >> 1, h = (ni & 1) * 2;
                    mma16816(c[mi][ni], aH[mi][0], aH[mi][1], aH[mi][2], aH[mi][3],
                             bhi[ks][bt][h], bhi[ks][bt][h + 1]);
                    mma16816(c[mi][ni], aH[mi][0], aH[mi][1], aH[mi][2], aH[mi][3],
                             bL[bt][h], bL[bt][h + 1]);
                    mma16816(c[mi][ni], aL[mi][0], aL[mi][1], aL[mi][2], aL[mi][3],
                             bhi[ks][bt][h], bhi[ks][bt][h + 1]);
                }
        }

        // ---- relu + per-row stats (4 rows/thread) ----
        float sm[4] = {0.f, 0.f, 0.f, 0.f}, sq[4] = {0.f, 0.f, 0.f, 0.f};
#pragma unroll
        for (int mi = 0; mi < 2; mi++)
#pragma unroll
            for (int ni = 0; ni < 8; ni++)
#pragma unroll
                for (int rr = 0; rr < 4; rr++) {
                    float h = fmaxf(c[mi][ni][rr], 0.f);
                    c[mi][ni][rr] = h;
                    int slot = mi * 2 + (rr >> 1);
                    sm[slot] += h;
                    sq[slot] = fmaf(h, h, sq[slot]);
                }
#pragma unroll
        for (int slot = 0; slot < 4; slot++) {
            sm[slot] += __shfl_xor_sync(0xffffffffu, sm[slot], 1);
            sq[slot] += __shfl_xor_sync(0xffffffffu, sq[slot], 1);
            sm[slot] += __shfl_xor_sync(0xffffffffu, sm[slot], 2);
            sq[slot] += __shfl_xor_sync(0xffffffffu, sq[slot], 2);
        }
        if ((lane & 3) == 0) {
#pragma unroll
            for (int slot = 0; slot < 4; slot++) {
                int row = Mb + (slot >> 1) * 16 + (slot & 1) * 8 + (lane >> 2);
                *(float2*)(smem + OFF_PART + (row * 2 + nw) * 8) = make_float2(sm[slot], sq[slot]);
            }
        }
        __syncthreads();   // S2

        // ---- normalize + stage ----
        float2 gg[8], tt[8];
#pragma unroll
        for (int ni = 0; ni < 8; ni++) {
            int cb = (Nb + ni * 8 + (lane & 3) * 2) * 4;
            gg[ni] = *(const float2*)(smem + OFF_PRM + 512 + cb);
            tt[ni] = *(const float2*)(smem + OFF_PRM + 1024 + cb);
        }
        float mu[4], rs[4];
#pragma unroll
        for (int slot = 0; slot < 4; slot++) {
            int row = Mb + (slot >> 1) * 16 + (slot & 1) * 8 + (lane >> 2);
            float2 p0 = *(const float2*)(smem + OFF_PART + (row * 2 + 0) * 8);
            float2 p1 = *(const float2*)(smem + OFF_PART + (row * 2 + 1) * 8);
            float sum = p0.x + p1.x, ss = p0.y + p1.y;
            mu[slot] = sum * (1.0f / 128.0f);
            float var = ss * (1.0f / 128.0f) - mu[slot] * mu[slot];
            rs[slot] = rsqrtf(var + 1e-5f);
        }
#pragma unroll
        for (int mi = 0; mi < 2; mi++)
#pragma unroll
            for (int rh = 0; rh < 2; rh++) {
                int slot = mi * 2 + rh;
                int row = Mb + mi * 16 + rh * 8 + (lane >> 2);
                char* rp = smem + OFF_SH + row * 528;
#pragma unroll
                for (int ni = 0; ni < 8; ni++) {
                    float y0 = (c[mi][ni][rh * 2 + 0] - mu[slot]) * rs[slot] * gg[ni].x + tt[ni].x;
                    float y1 = (c[mi][ni][rh * 2 + 1] - mu[slot]) * rs[slot] * gg[ni].y + tt[ni].y;
                    *(float2*)(rp + (Nb + ni * 8 + (lane & 3) * 2) * 4) = make_float2(y0, y1);
                }
            }
        __syncthreads();   // S3

        // ---- scatter: 2 endpoints x 128 edges x 32 quads, coalesced red.v4 ----
#pragma unroll 8
        for (int r2 = 0; r2 < 32; r2++) {
            int item = tid + 256 * r2;
            int q = item & 31;
            int rowsel = item >> 5;
            int ep = rowsel >> 7, m = rowsel & 127;
            if (base_e + m < E) {
                int node = ((const int*)(smem + (ep ? OFF_DST : OFF_SRC)))[m];
                float4 v = *(const float4*)(smem + OFF_SH + m * 528 + q * 16);
                float* p = out + (size_t)node * 128 + q * 4;
                asm volatile("red.global.add.v4.f32 [%0], {%1,%2,%3,%4};"
                             :: "l"(p), "f"(v.x), "f"(v.y), "f"(v.z), "f"(v.w)
                             : "memory");
            }
        }
        __syncthreads();   // S4
        tile = next;
    }

    // ======================= grid barrier =======================
    __threadfence();       // order this thread's reds before barrier
    __syncthreads();
    if (tid == 0) {
        unsigned s = atomicAdd(&g_bar_sense, 0u);
        unsigned prev = atomicAdd(&g_bar_count, 1u);
        if (prev == gridDim.x - 1) {
            atomicExch(&g_bar_count, 0u);
            atomicExch(&g_bar_sense, s ^ 1u);
        } else {
            while (atomicAdd(&g_bar_sense, 0u) == s) { __nanosleep(64); }
        }
    }
    __syncthreads();
    __threadfence();

    // ======================= finalize =======================
    {
        const int n4 = Nn * 32;
        float4* out4 = (float4*)out;
        for (int i = blockIdx.x * 256 + tid; i < n4; i += step * 256) {
            int row = i >> 5;
            float inv = 1.0f / fmaxf(g_degree[row], 1.0f);
            float4 v = out4[i];
            v.x *= inv; v.y *= inv; v.z *= inv; v.w *= inv;
            out4[i] = v;
        }
    }
}

extern "C" void kernel_launch(void* const* d_in, const int* in_sizes, int n_in,
                              void* d_out, int out_size) {
    const float* edge_attr = (const float*)d_in[0];
    const float* W         = (const float*)d_in[1];
    const float* b         = (const float*)d_in[2];
    const float* gamma     = (const float*)d_in[3];
    const float* beta      = (const float*)d_in[4];
    const long long* eidx  = (const long long*)d_in[5];
    float* out = (float*)d_out;

    const int E  = in_sizes[0] / 64;
    const int N  = out_size / 128;
    const int n4 = out_size / 4;

    static int nsm = 0;
    if (nsm == 0) {
        cudaDeviceGetAttribute(&nsm, cudaDevAttrMultiProcessorCount, 0);
        if (nsm <= 0) nsm = 148;
        cudaFuncSetAttribute(edge2node_fused,
                             cudaFuncAttributeMaxDynamicSharedMemorySize, SMEM_TOTAL);
    }

    zero_kernel<<<(n4 + 255) / 256, 256>>>((float4*)out, n4, N);

    const int ntiles = (E + 127) / 128;
    edge2node_fused<<<nsm, 256, SMEM_TOTAL>>>(edge_attr, W, b, gamma, beta, eidx,
                                              out, E, ntiles, N);
}